// round 1
// baseline (speedup 1.0000x reference)
#include <cuda_runtime.h>
#include <math.h>

#define N_NODE  50000
#define N_EDGE  1000000
#define D_E     64
#define D_IN    128

// ---------------- device scratch (static; no allocations allowed) ----------------
__device__ float    g_hs[N_NODE * D_E];     // x_s @ W_src^T
__device__ float    g_ht[N_NODE * D_E];     // x_t @ W_tgt^T
__device__ float    g_as[N_NODE];           // hs . w_attn
__device__ float    g_at[N_NODE];           // ht . w_attn
__device__ float    g_v[D_E];               // W_edge^T @ w_attn
__device__ unsigned g_mkey[N_NODE];         // ordered-float max keys per src
__device__ float    g_denom[N_NODE];        // softmax denominators per src
__device__ float    g_score[N_EDGE];        // post-leaky scores

// ---------------- helpers ----------------
__device__ __forceinline__ unsigned fkey(float f) {
    unsigned u = __float_as_uint(f);
    return (u & 0x80000000u) ? ~u : (u | 0x80000000u);
}
__device__ __forceinline__ float fdecode(unsigned k) {
    return (k & 0x80000000u) ? __uint_as_float(k & 0x7fffffffu)
                             : __uint_as_float(~k);
}
// Detect whether edge_index is int64 or int32 (JAX may silently downcast).
// If int32, an int64 read combines two values < 50000 -> >= 2^32 unless the
// high half is exactly 0 (prob ~(2e-5)^4 over 4 probes).
__device__ __forceinline__ bool idx_is64(const void* p) {
    const long long* q = (const long long*)p;
    bool ok = true;
#pragma unroll
    for (int i = 0; i < 4; i++)
        ok = ok && ((unsigned long long)q[i] < (unsigned long long)N_NODE);
    return ok;
}
__device__ __forceinline__ long long get_idx(const void* p, bool is64, size_t pos) {
    return is64 ? ((const long long*)p)[pos]
                : (long long)((const int*)p)[pos];
}

// ---------------- K0: init maxkeys/denoms + v = W_edge^T @ w_attn ----------------
__global__ void init_kernel(const float* __restrict__ W_edge,
                            const float* __restrict__ w_attn) {
    int i = blockIdx.x * blockDim.x + threadIdx.x;
    if (i < N_NODE) { g_mkey[i] = 0u; g_denom[i] = 0.f; }
    if (blockIdx.x == 0 && threadIdx.x < D_E) {
        float s = 0.f;
#pragma unroll 8
        for (int j = 0; j < D_E; j++) s += W_edge[j * D_E + threadIdx.x] * w_attn[j];
        g_v[threadIdx.x] = s;
    }
}

// ---------------- K1: node projections hs/ht + scalar scores a_s/a_t ----------------
// One thread per node; W^T staged in smem, read as float4 broadcasts (FFMA-bound).
__global__ void __launch_bounds__(256) node_proj_kernel(
    const float* __restrict__ x_s, const float* __restrict__ x_t,
    const float* __restrict__ W_src, const float* __restrict__ W_tgt,
    const float* __restrict__ w_attn) {
    __shared__ float WT[D_IN * D_E];   // WT[k*64+j] = W[j*128+k]  (32 KB)
    __shared__ float wa[D_E];

    const float* x; const float* W; float* hout; float* aout;
    if (blockIdx.y == 0) { x = x_s; W = W_src; hout = g_hs; aout = g_as; }
    else                 { x = x_t; W = W_tgt; hout = g_ht; aout = g_at; }

    for (int i = threadIdx.x; i < D_E * D_IN; i += blockDim.x) {
        int j = i >> 7, k = i & 127;
        WT[k * D_E + j] = W[i];
    }
    if (threadIdx.x < D_E) wa[threadIdx.x] = w_attn[threadIdx.x];
    __syncthreads();

    int n = blockIdx.x * blockDim.x + threadIdx.x;
    if (n >= N_NODE) return;

    float acc[D_E];
#pragma unroll
    for (int j = 0; j < D_E; j++) acc[j] = 0.f;

    const float4* xr = (const float4*)(x + (size_t)n * D_IN);
    for (int kc = 0; kc < 32; kc++) {
        float4 xv = xr[kc];
        float xa[4] = {xv.x, xv.y, xv.z, xv.w};
#pragma unroll
        for (int c = 0; c < 4; c++) {
            const float* wrow = &WT[(4 * kc + c) * D_E];
#pragma unroll
            for (int j4 = 0; j4 < D_E; j4 += 4) {
                float4 w = *(const float4*)&wrow[j4];
                acc[j4 + 0] += xa[c] * w.x;
                acc[j4 + 1] += xa[c] * w.y;
                acc[j4 + 2] += xa[c] * w.z;
                acc[j4 + 3] += xa[c] * w.w;
            }
        }
    }
    float av = 0.f;
#pragma unroll
    for (int j = 0; j < D_E; j++) av += acc[j] * wa[j];
    aout[n] = av;
    float4* ho = (float4*)(hout + (size_t)n * D_E);
#pragma unroll
    for (int j4 = 0; j4 < 16; j4++)
        ho[j4] = make_float4(acc[4 * j4], acc[4 * j4 + 1], acc[4 * j4 + 2], acc[4 * j4 + 3]);
}

// ---------------- K2: per-edge score + atomic segment max ----------------
// 4 lanes per edge; score = ea.v + a_s[src] + a_t[tgt], leaky-relu(0.2).
__global__ void __launch_bounds__(256) score_kernel(
    const float* __restrict__ edge_attr, const void* __restrict__ eidx) {
    __shared__ float v[D_E];
    if (threadIdx.x < D_E) v[threadIdx.x] = g_v[threadIdx.x];
    __syncthreads();

    long long t = (long long)blockIdx.x * 256 + threadIdx.x;
    long long e = t >> 2;
    int q = (int)(t & 3);
    if (e >= N_EDGE) return;

    const float4* row = (const float4*)(edge_attr + e * D_E);
    float p = 0.f;
#pragma unroll
    for (int i = 0; i < 4; i++) {
        float4 av = __ldcs(&row[q + 4 * i]);
        float4 vv = *(const float4*)&v[4 * (q + 4 * i)];
        p += av.x * vv.x + av.y * vv.y + av.z * vv.z + av.w * vv.w;
    }
    p += __shfl_xor_sync(0xffffffffu, p, 1);
    p += __shfl_xor_sync(0xffffffffu, p, 2);
    if (q == 0) {
        bool is64 = idx_is64(eidx);
        long long src = get_idx(eidx, is64, (size_t)e);
        long long tgt = get_idx(eidx, is64, (size_t)N_EDGE + e);
        float s = p + g_as[src] + g_at[tgt];
        s = (s >= 0.f) ? s : 0.2f * s;
        g_score[e] = s;
        atomicMax(&g_mkey[src], fkey(s));
    }
}

// ---------------- K3: softmax denominators ----------------
__global__ void __launch_bounds__(256) denom_kernel(const void* __restrict__ eidx) {
    long long e = (long long)blockIdx.x * 256 + threadIdx.x;
    if (e >= N_EDGE) return;
    bool is64 = idx_is64(eidx);
    long long src = get_idx(eidx, is64, (size_t)e);
    float s = g_score[e];
    float m = fdecode(g_mkey[src]);
    atomicAdd(&g_denom[src], expf(s - m));
}

// ---------------- K4: fused edge GEMM + gather + softmax weight + RMSNorm ----------------
// Block tile: 128 edges x 64 features, K=64. Threads (32x8), 4x8 per-thread tile.
// XOR swizzle keeps both the GEMM reads and the warp-per-edge epilogue conflict-free.
__global__ void __launch_bounds__(256) out_kernel(
    const float* __restrict__ edge_attr, const void* __restrict__ eidx,
    const float* __restrict__ W_edge, const float* __restrict__ norm_w,
    float* __restrict__ out) {
    __shared__ float Wsh[D_E * D_E];    // [j][k], broadcast reads (16 KB)
    __shared__ float eaSh[128 * D_E];   // swizzled ea tile; reused for hedge (32 KB)

    const bool is64 = idx_is64(eidx);
    const int tid = threadIdx.x;
    const int tx = tid & 31, ty = tid >> 5;

    for (int i = tid; i < D_E * D_E; i += 256) Wsh[i] = W_edge[i];

    long long e0 = (long long)blockIdx.x * 128;
    for (int i = tid; i < 128 * D_E; i += 256) {
        int el = i >> 6, k = i & 63;
        long long e = e0 + el;
        float val = (e < N_EDGE) ? __ldcs(&edge_attr[e * D_E + k]) : 0.f;
        eaSh[el * D_E + (k ^ (el & 31))] = val;
    }
    __syncthreads();

    float acc[4][8];
#pragma unroll
    for (int ii = 0; ii < 4; ii++)
#pragma unroll
        for (int jj = 0; jj < 8; jj++) acc[ii][jj] = 0.f;

#pragma unroll 4
    for (int k = 0; k < D_E; k++) {
        float a[4], w[8];
#pragma unroll
        for (int ii = 0; ii < 4; ii++) a[ii] = eaSh[(tx + 32 * ii) * D_E + (k ^ tx)];
#pragma unroll
        for (int jj = 0; jj < 8; jj++) w[jj] = Wsh[(ty + 8 * jj) * D_E + k];
#pragma unroll
        for (int ii = 0; ii < 4; ii++)
#pragma unroll
            for (int jj = 0; jj < 8; jj++) acc[ii][jj] += a[ii] * w[jj];
    }
    __syncthreads();

    // write hedge back (same swizzle: col = j ^ (el&31))
#pragma unroll
    for (int ii = 0; ii < 4; ii++) {
        int el = tx + 32 * ii;
#pragma unroll
        for (int jj = 0; jj < 8; jj++) {
            int j = ty + 8 * jj;
            eaSh[el * D_E + (j ^ tx)] = acc[ii][jj];
        }
    }
    __syncthreads();

    // epilogue: warp ty owns 16 edges; lane = feature (j0=lane, j1=lane+32)
    for (int t = 0; t < 16; t++) {
        int el = ty * 16 + t;
        long long e = e0 + el;
        if (e >= N_EDGE) break;
        long long src = get_idx(eidx, is64, (size_t)e);
        long long tgt = get_idx(eidx, is64, (size_t)N_EDGE + e);
        float s   = g_score[e];
        float m   = fdecode(g_mkey[src]);
        float den = g_denom[src];
        float alpha = expf(s - m) / den;

        int j0 = tx, j1 = tx + 32;
        int sw = el & 31;
        float h0 = eaSh[el * D_E + (j0 ^ sw)] + g_hs[src * D_E + j0] + g_ht[tgt * D_E + j0];
        float h1 = eaSh[el * D_E + (j1 ^ sw)] + g_hs[src * D_E + j1] + g_ht[tgt * D_E + j1];
        float y0 = h0 * alpha, y1 = h1 * alpha;
        float ss = y0 * y0 + y1 * y1;
#pragma unroll
        for (int o = 16; o; o >>= 1) ss += __shfl_xor_sync(0xffffffffu, ss, o);
        float r = rsqrtf(ss * (1.f / 64.f) + 1.1920929e-7f);
        out[e * D_E + j0] = y0 * r * __ldg(&norm_w[j0]);
        out[e * D_E + j1] = y1 * r * __ldg(&norm_w[j1]);
    }
}

// ---------------- launch ----------------
extern "C" void kernel_launch(void* const* d_in, const int* in_sizes, int n_in,
                              void* d_out, int out_size) {
    const float* x_s    = (const float*)d_in[0];
    const float* x_t    = (const float*)d_in[1];
    const void*  eidx   = d_in[2];
    const float* ea     = (const float*)d_in[3];
    // d_in[4] = x_u (unused by the reference)
    const float* W_src  = (const float*)d_in[5];
    const float* W_tgt  = (const float*)d_in[6];
    const float* W_edge = (const float*)d_in[7];
    const float* w_attn = (const float*)d_in[8];
    const float* norm_w = (const float*)d_in[9];
    float* out = (float*)d_out;

    init_kernel<<<(N_NODE + 255) / 256, 256>>>(W_edge, w_attn);

    dim3 g1((N_NODE + 255) / 256, 2);
    node_proj_kernel<<<g1, 256>>>(x_s, x_t, W_src, W_tgt, w_attn);

    long long score_threads = (long long)N_EDGE * 4;
    score_kernel<<<(unsigned)((score_threads + 255) / 256), 256>>>(ea, eidx);

    denom_kernel<<<(N_EDGE + 255) / 256, 256>>>(eidx);

    out_kernel<<<(N_EDGE + 127) / 128, 256>>>(ea, eidx, W_edge, norm_w, out);
}

// round 2
// speedup vs baseline: 1.3831x; 1.3831x over previous
#include <cuda_runtime.h>
#include <math.h>

#define N_NODE  50000
#define N_EDGE  1000000
#define D_E     64
#define D_IN    128

// ---------------- device scratch (static; no allocations allowed) ----------------
__device__ float    g_hs[N_NODE * D_E];     // x_s @ W_src^T
__device__ float    g_ht[N_NODE * D_E];     // x_t @ W_tgt^T
__device__ float    g_as[N_NODE];           // hs . w_attn
__device__ float    g_at[N_NODE];           // ht . w_attn
__device__ float    g_v[D_E];               // W_edge^T @ w_attn
__device__ unsigned g_mkey[N_NODE];         // ordered-float max keys per src
__device__ float    g_denom[N_NODE];        // softmax denominators per src
__device__ float    g_score[N_EDGE];        // post-leaky scores

// ---------------- helpers ----------------
__device__ __forceinline__ unsigned fkey(float f) {
    unsigned u = __float_as_uint(f);
    return (u & 0x80000000u) ? ~u : (u | 0x80000000u);
}
__device__ __forceinline__ float fdecode(unsigned k) {
    return (k & 0x80000000u) ? __uint_as_float(k & 0x7fffffffu)
                             : __uint_as_float(~k);
}
__device__ __forceinline__ bool idx_is64(const void* p) {
    const long long* q = (const long long*)p;
    bool ok = true;
#pragma unroll
    for (int i = 0; i < 4; i++)
        ok = ok && ((unsigned long long)q[i] < (unsigned long long)N_NODE);
    return ok;
}
__device__ __forceinline__ long long get_idx(const void* p, bool is64, size_t pos) {
    return is64 ? ((const long long*)p)[pos]
                : (long long)((const int*)p)[pos];
}
// tf32 split: hi = rna(x), lo = x - hi (hw truncation of lo adds ~2^-22 rel err)
__device__ __forceinline__ void tf32_split(float x, unsigned& hi, unsigned& lo) {
    unsigned h;
    asm("cvt.rna.tf32.f32 %0, %1;" : "=r"(h) : "f"(x));
    hi = h;
    lo = __float_as_uint(x - __uint_as_float(h));
}
__device__ __forceinline__ void mma_tf32(float c[4], const unsigned a[4], const unsigned b[2]) {
    asm volatile(
        "mma.sync.aligned.m16n8k8.row.col.f32.tf32.tf32.f32 "
        "{%0,%1,%2,%3}, {%4,%5,%6,%7}, {%8,%9}, {%0,%1,%2,%3};"
        : "+f"(c[0]), "+f"(c[1]), "+f"(c[2]), "+f"(c[3])
        : "r"(a[0]), "r"(a[1]), "r"(a[2]), "r"(a[3]), "r"(b[0]), "r"(b[1]));
}

// ---------------- K0: init maxkeys/denoms + v = W_edge^T @ w_attn ----------------
__global__ void init_kernel(const float* __restrict__ W_edge,
                            const float* __restrict__ w_attn) {
    int i = blockIdx.x * blockDim.x + threadIdx.x;
    if (i < N_NODE) { g_mkey[i] = 0u; g_denom[i] = 0.f; }
    if (blockIdx.x == 0 && threadIdx.x < D_E) {
        float s = 0.f;
#pragma unroll 8
        for (int j = 0; j < D_E; j++) s += W_edge[j * D_E + threadIdx.x] * w_attn[j];
        g_v[threadIdx.x] = s;
    }
}

// ---------------- K1: node projections hs/ht + scalar scores a_s/a_t ----------------
__global__ void __launch_bounds__(256) node_proj_kernel(
    const float* __restrict__ x_s, const float* __restrict__ x_t,
    const float* __restrict__ W_src, const float* __restrict__ W_tgt,
    const float* __restrict__ w_attn) {
    __shared__ float WT[D_IN * D_E];
    __shared__ float wa[D_E];

    const float* x; const float* W; float* hout; float* aout;
    if (blockIdx.y == 0) { x = x_s; W = W_src; hout = g_hs; aout = g_as; }
    else                 { x = x_t; W = W_tgt; hout = g_ht; aout = g_at; }

    for (int i = threadIdx.x; i < D_E * D_IN; i += blockDim.x) {
        int j = i >> 7, k = i & 127;
        WT[k * D_E + j] = W[i];
    }
    if (threadIdx.x < D_E) wa[threadIdx.x] = w_attn[threadIdx.x];
    __syncthreads();

    int n = blockIdx.x * blockDim.x + threadIdx.x;
    if (n >= N_NODE) return;

    float acc[D_E];
#pragma unroll
    for (int j = 0; j < D_E; j++) acc[j] = 0.f;

    const float4* xr = (const float4*)(x + (size_t)n * D_IN);
    for (int kc = 0; kc < 32; kc++) {
        float4 xv = xr[kc];
        float xa[4] = {xv.x, xv.y, xv.z, xv.w};
#pragma unroll
        for (int c = 0; c < 4; c++) {
            const float* wrow = &WT[(4 * kc + c) * D_E];
#pragma unroll
            for (int j4 = 0; j4 < D_E; j4 += 4) {
                float4 w = *(const float4*)&wrow[j4];
                acc[j4 + 0] += xa[c] * w.x;
                acc[j4 + 1] += xa[c] * w.y;
                acc[j4 + 2] += xa[c] * w.z;
                acc[j4 + 3] += xa[c] * w.w;
            }
        }
    }
    float av = 0.f;
#pragma unroll
    for (int j = 0; j < D_E; j++) av += acc[j] * wa[j];
    aout[n] = av;
    float4* ho = (float4*)(hout + (size_t)n * D_E);
#pragma unroll
    for (int j4 = 0; j4 < 16; j4++)
        ho[j4] = make_float4(acc[4 * j4], acc[4 * j4 + 1], acc[4 * j4 + 2], acc[4 * j4 + 3]);
}

// ---------------- K2: per-edge score + atomic segment max ----------------
__global__ void __launch_bounds__(256) score_kernel(
    const float* __restrict__ edge_attr, const void* __restrict__ eidx) {
    __shared__ float v[D_E];
    if (threadIdx.x < D_E) v[threadIdx.x] = g_v[threadIdx.x];
    __syncthreads();

    long long t = (long long)blockIdx.x * 256 + threadIdx.x;
    long long e = t >> 2;
    int q = (int)(t & 3);
    if (e >= N_EDGE) return;

    const float4* row = (const float4*)(edge_attr + e * D_E);
    float p = 0.f;
#pragma unroll
    for (int i = 0; i < 4; i++) {
        float4 av = __ldcs(&row[q + 4 * i]);
        float4 vv = *(const float4*)&v[4 * (q + 4 * i)];
        p += av.x * vv.x + av.y * vv.y + av.z * vv.z + av.w * vv.w;
    }
    p += __shfl_xor_sync(0xffffffffu, p, 1);
    p += __shfl_xor_sync(0xffffffffu, p, 2);
    if (q == 0) {
        bool is64 = idx_is64(eidx);
        long long src = get_idx(eidx, is64, (size_t)e);
        long long tgt = get_idx(eidx, is64, (size_t)N_EDGE + e);
        float s = p + g_as[src] + g_at[tgt];
        s = (s >= 0.f) ? s : 0.2f * s;
        g_score[e] = s;
        atomicMax(&g_mkey[src], fkey(s));
    }
}

// ---------------- K3: softmax denominators ----------------
__global__ void __launch_bounds__(256) denom_kernel(const void* __restrict__ eidx) {
    long long e = (long long)blockIdx.x * 256 + threadIdx.x;
    if (e >= N_EDGE) return;
    bool is64 = idx_is64(eidx);
    long long src = get_idx(eidx, is64, (size_t)e);
    float s = g_score[e];
    float m = fdecode(g_mkey[src]);
    atomicAdd(&g_denom[src], expf(s - m));
}

// ---------------- K4: tensor-core edge GEMM + gather + softmax + RMSNorm ----------------
// 128 edges x 64 features per block (8 warps; warp owns 16 edges).
// tf32 3-term split (hi*hi + hi*lo + lo*hi) => ~fp32 accuracy on tensor pipe.
// Smem tiles use XOR swizzle col' = k ^ 4*(row&7): all fragment LDS conflict-free.
__global__ void __launch_bounds__(256) out_kernel(
    const float* __restrict__ edge_attr, const void* __restrict__ eidx,
    const float* __restrict__ W_edge, const float* __restrict__ norm_w,
    float* __restrict__ out) {
    __shared__ float eaSh[128 * D_E];   // 32 KB, swizzled
    __shared__ float Wsh[D_E * D_E];    // 16 KB, swizzled: Wsh[n][k] = W_edge[n*64+k]

    const bool is64 = idx_is64(eidx);
    const int tid  = threadIdx.x;
    const int lane = tid & 31, warp = tid >> 5;
    const int g = lane >> 2, tig = lane & 3;

    long long e0 = (long long)blockIdx.x * 128;

    for (int i = tid; i < D_E * D_E; i += 256) {
        int n = i >> 6, k = i & 63;
        Wsh[n * D_E + (k ^ (4 * (n & 7)))] = W_edge[i];
    }
    for (int i = tid; i < 128 * D_E; i += 256) {
        int el = i >> 6, k = i & 63;
        long long e = e0 + el;
        float val = (e < N_EDGE) ? __ldcs(&edge_attr[e * D_E + k]) : 0.f;
        eaSh[el * D_E + (k ^ (4 * (el & 7)))] = val;
    }
    __syncthreads();

    // ---- MMA mainloop: warp computes rows [warp*16, warp*16+16) x all 64 cols ----
    float c[8][4];
#pragma unroll
    for (int nt = 0; nt < 8; nt++)
#pragma unroll
        for (int r = 0; r < 4; r++) c[nt][r] = 0.f;

    const int wr0 = warp * 16;          // (wr0+g)&7 == g, (wr0+8+g)&7 == g
    const int sw  = 4 * g;              // swizzle term for all this thread's rows

#pragma unroll
    for (int kt = 0; kt < 8; kt++) {
        const int k0 = kt * 8;
        unsigned ah[4], al[4];
        tf32_split(eaSh[(wr0 + g)     * D_E + ((k0 + tig)     ^ sw)], ah[0], al[0]);
        tf32_split(eaSh[(wr0 + 8 + g) * D_E + ((k0 + tig)     ^ sw)], ah[1], al[1]);
        tf32_split(eaSh[(wr0 + g)     * D_E + ((k0 + tig + 4) ^ sw)], ah[2], al[2]);
        tf32_split(eaSh[(wr0 + 8 + g) * D_E + ((k0 + tig + 4) ^ sw)], ah[3], al[3]);
#pragma unroll
        for (int nt = 0; nt < 8; nt++) {
            const int n = nt * 8 + g;   // n&7 == g  -> same swizzle term
            unsigned bh[2], bl[2];
            tf32_split(Wsh[n * D_E + ((k0 + tig)     ^ sw)], bh[0], bl[0]);
            tf32_split(Wsh[n * D_E + ((k0 + tig + 4) ^ sw)], bh[1], bl[1]);
            mma_tf32(c[nt], ah, bh);
            mma_tf32(c[nt], ah, bl);
            mma_tf32(c[nt], al, bh);
        }
    }

    // ---- epilogue in fragment layout ----
    // thread holds rows eA = e0+wr0+g, eB = eA+8; cols 2*tig + 8*nt (+1)
    long long eA = e0 + wr0 + g;
    long long eB = eA + 8;
    bool vA = (eA < N_EDGE), vB = (eB < N_EDGE);

    float2 nw[8];
#pragma unroll
    for (int nt = 0; nt < 8; nt++)
        nw[nt] = __ldg(&((const float2*)norm_w)[nt * 4 + tig]);

    float alphaA = 0.f, alphaB = 0.f;
    if (vA) {
        long long src = get_idx(eidx, is64, (size_t)eA);
        long long tgt = get_idx(eidx, is64, (size_t)N_EDGE + eA);
        float s = g_score[eA];
        alphaA = expf(s - fdecode(g_mkey[src])) / g_denom[src];
        const float2* hs = (const float2*)&g_hs[src * D_E];
        const float2* ht = (const float2*)&g_ht[tgt * D_E];
#pragma unroll
        for (int nt = 0; nt < 8; nt++) {
            float2 a = hs[nt * 4 + tig], b = ht[nt * 4 + tig];
            c[nt][0] += a.x + b.x;
            c[nt][1] += a.y + b.y;
        }
    }
    if (vB) {
        long long src = get_idx(eidx, is64, (size_t)eB);
        long long tgt = get_idx(eidx, is64, (size_t)N_EDGE + eB);
        float s = g_score[eB];
        alphaB = expf(s - fdecode(g_mkey[src])) / g_denom[src];
        const float2* hs = (const float2*)&g_hs[src * D_E];
        const float2* ht = (const float2*)&g_ht[tgt * D_E];
#pragma unroll
        for (int nt = 0; nt < 8; nt++) {
            float2 a = hs[nt * 4 + tig], b = ht[nt * 4 + tig];
            c[nt][2] += a.x + b.x;
            c[nt][3] += a.y + b.y;
        }
    }

    float ssA = 0.f, ssB = 0.f;
#pragma unroll
    for (int nt = 0; nt < 8; nt++) {
        c[nt][0] *= alphaA; c[nt][1] *= alphaA;
        c[nt][2] *= alphaB; c[nt][3] *= alphaB;
        ssA += c[nt][0] * c[nt][0] + c[nt][1] * c[nt][1];
        ssB += c[nt][2] * c[nt][2] + c[nt][3] * c[nt][3];
    }
    // reduce over the 4 lanes of this row group
    ssA += __shfl_xor_sync(0xffffffffu, ssA, 1);
    ssA += __shfl_xor_sync(0xffffffffu, ssA, 2);
    ssB += __shfl_xor_sync(0xffffffffu, ssB, 1);
    ssB += __shfl_xor_sync(0xffffffffu, ssB, 2);
    float rA = rsqrtf(ssA * (1.f / 64.f) + 1.1920929e-7f);
    float rB = rsqrtf(ssB * (1.f / 64.f) + 1.1920929e-7f);

    if (vA) {
        float2* o = (float2*)&out[eA * D_E];
#pragma unroll
        for (int nt = 0; nt < 8; nt++)
            o[nt * 4 + tig] = make_float2(c[nt][0] * rA * nw[nt].x,
                                          c[nt][1] * rA * nw[nt].y);
    }
    if (vB) {
        float2* o = (float2*)&out[eB * D_E];
#pragma unroll
        for (int nt = 0; nt < 8; nt++)
            o[nt * 4 + tig] = make_float2(c[nt][2] * rB * nw[nt].x,
                                          c[nt][3] * rB * nw[nt].y);
    }
}

// ---------------- launch ----------------
extern "C" void kernel_launch(void* const* d_in, const int* in_sizes, int n_in,
                              void* d_out, int out_size) {
    const float* x_s    = (const float*)d_in[0];
    const float* x_t    = (const float*)d_in[1];
    const void*  eidx   = d_in[2];
    const float* ea     = (const float*)d_in[3];
    const float* W_src  = (const float*)d_in[5];
    const float* W_tgt  = (const float*)d_in[6];
    const float* W_edge = (const float*)d_in[7];
    const float* w_attn = (const float*)d_in[8];
    const float* norm_w = (const float*)d_in[9];
    float* out = (float*)d_out;

    init_kernel<<<(N_NODE + 255) / 256, 256>>>(W_edge, w_attn);

    dim3 g1((N_NODE + 255) / 256, 2);
    node_proj_kernel<<<g1, 256>>>(x_s, x_t, W_src, W_tgt, w_attn);

    long long score_threads = (long long)N_EDGE * 4;
    score_kernel<<<(unsigned)((score_threads + 255) / 256), 256>>>(ea, eidx);

    denom_kernel<<<(N_EDGE + 255) / 256, 256>>>(eidx);

    out_kernel<<<(N_EDGE + 127) / 128, 256>>>(ea, eidx, W_edge, norm_w, out);
}

// round 3
// speedup vs baseline: 1.7323x; 1.2525x over previous
#include <cuda_runtime.h>
#include <math.h>

#define N_NODE  50000
#define N_EDGE  1000000
#define D_E     64
#define D_IN    128

// ---------------- device scratch (static; no allocations allowed) ----------------
__device__ float    g_hs[N_NODE * D_E];     // x_s @ W_src^T
__device__ float    g_ht[N_NODE * D_E];     // x_t @ W_tgt^T
__device__ float    g_as[N_NODE];           // hs . w_attn
__device__ float    g_at[N_NODE];           // ht . w_attn
__device__ float    g_v[D_E];               // W_edge^T @ w_attn
__device__ unsigned g_mkey[N_NODE];         // ordered-float max keys per src
__device__ float    g_denom[N_NODE];        // softmax denominators per src
__device__ float    g_score[N_EDGE];        // post-leaky scores
__device__ unsigned g_Wh[D_E * 32];         // W_edge hi plane, packed bf16x2: [n][k/2]
__device__ unsigned g_Wl[D_E * 32];         // W_edge lo plane, packed bf16x2

// ---------------- helpers ----------------
__device__ __forceinline__ unsigned fkey(float f) {
    unsigned u = __float_as_uint(f);
    return (u & 0x80000000u) ? ~u : (u | 0x80000000u);
}
__device__ __forceinline__ float fdecode(unsigned k) {
    return (k & 0x80000000u) ? __uint_as_float(k & 0x7fffffffu)
                             : __uint_as_float(~k);
}
__device__ __forceinline__ bool idx_is64(const void* p) {
    const long long* q = (const long long*)p;
    bool ok = true;
#pragma unroll
    for (int i = 0; i < 4; i++)
        ok = ok && ((unsigned long long)q[i] < (unsigned long long)N_NODE);
    return ok;
}
__device__ __forceinline__ long long get_idx(const void* p, bool is64, size_t pos) {
    return is64 ? ((const long long*)p)[pos]
                : (long long)((const int*)p)[pos];
}
// pack float2 -> bf16x2 (low half = v.x), plus residual bf16x2 lo plane
__device__ __forceinline__ void bf16_split2(float x0, float x1, unsigned& hi, unsigned& lo) {
    unsigned h;
    asm("cvt.rn.bf16x2.f32 %0, %1, %2;" : "=r"(h) : "f"(x1), "f"(x0));
    float h0 = __uint_as_float(h << 16);
    float h1 = __uint_as_float(h & 0xFFFF0000u);
    float l0 = x0 - h0;
    float l1 = x1 - h1;
    unsigned l;
    asm("cvt.rn.bf16x2.f32 %0, %1, %2;" : "=r"(l) : "f"(l1), "f"(l0));
    hi = h; lo = l;
}
__device__ __forceinline__ void mma_bf16(float c[4], const unsigned a[4], unsigned b0, unsigned b1) {
    asm volatile(
        "mma.sync.aligned.m16n8k16.row.col.f32.bf16.bf16.f32 "
        "{%0,%1,%2,%3}, {%4,%5,%6,%7}, {%8,%9}, {%0,%1,%2,%3};"
        : "+f"(c[0]), "+f"(c[1]), "+f"(c[2]), "+f"(c[3])
        : "r"(a[0]), "r"(a[1]), "r"(a[2]), "r"(a[3]), "r"(b0), "r"(b1));
}

// ---------------- K0: init + v = W_edge^T @ w_attn + W bf16 split ----------------
__global__ void init_kernel(const float* __restrict__ W_edge,
                            const float* __restrict__ w_attn) {
    int i = blockIdx.x * blockDim.x + threadIdx.x;
    if (i < N_NODE) { g_mkey[i] = 0u; g_denom[i] = 0.f; }
    if (i < D_E * 32) {              // pre-split W_edge into bf16 hi/lo planes
        int n = i >> 5, k2 = i & 31;
        float w0 = W_edge[n * D_E + 2 * k2];
        float w1 = W_edge[n * D_E + 2 * k2 + 1];
        unsigned h, l;
        bf16_split2(w0, w1, h, l);
        g_Wh[i] = h; g_Wl[i] = l;
    }
    if (blockIdx.x == 0 && threadIdx.x < D_E) {
        float s = 0.f;
#pragma unroll 8
        for (int j = 0; j < D_E; j++) s += W_edge[j * D_E + threadIdx.x] * w_attn[j];
        g_v[threadIdx.x] = s;
    }
}

// ---------------- K1: node projections hs/ht + scalar scores a_s/a_t ----------------
__global__ void __launch_bounds__(256) node_proj_kernel(
    const float* __restrict__ x_s, const float* __restrict__ x_t,
    const float* __restrict__ W_src, const float* __restrict__ W_tgt,
    const float* __restrict__ w_attn) {
    __shared__ float WT[D_IN * D_E];
    __shared__ float wa[D_E];

    const float* x; const float* W; float* hout; float* aout;
    if (blockIdx.y == 0) { x = x_s; W = W_src; hout = g_hs; aout = g_as; }
    else                 { x = x_t; W = W_tgt; hout = g_ht; aout = g_at; }

    for (int i = threadIdx.x; i < D_E * D_IN; i += blockDim.x) {
        int j = i >> 7, k = i & 127;
        WT[k * D_E + j] = W[i];
    }
    if (threadIdx.x < D_E) wa[threadIdx.x] = w_attn[threadIdx.x];
    __syncthreads();

    int n = blockIdx.x * blockDim.x + threadIdx.x;
    if (n >= N_NODE) return;

    float acc[D_E];
#pragma unroll
    for (int j = 0; j < D_E; j++) acc[j] = 0.f;

    const float4* xr = (const float4*)(x + (size_t)n * D_IN);
    for (int kc = 0; kc < 32; kc++) {
        float4 xv = xr[kc];
        float xa[4] = {xv.x, xv.y, xv.z, xv.w};
#pragma unroll
        for (int c = 0; c < 4; c++) {
            const float* wrow = &WT[(4 * kc + c) * D_E];
#pragma unroll
            for (int j4 = 0; j4 < D_E; j4 += 4) {
                float4 w = *(const float4*)&wrow[j4];
                acc[j4 + 0] += xa[c] * w.x;
                acc[j4 + 1] += xa[c] * w.y;
                acc[j4 + 2] += xa[c] * w.z;
                acc[j4 + 3] += xa[c] * w.w;
            }
        }
    }
    float av = 0.f;
#pragma unroll
    for (int j = 0; j < D_E; j++) av += acc[j] * wa[j];
    aout[n] = av;
    float4* ho = (float4*)(hout + (size_t)n * D_E);
#pragma unroll
    for (int j4 = 0; j4 < 16; j4++)
        ho[j4] = make_float4(acc[4 * j4], acc[4 * j4 + 1], acc[4 * j4 + 2], acc[4 * j4 + 3]);
}

// ---------------- K2: per-edge score + atomic segment max ----------------
__global__ void __launch_bounds__(256) score_kernel(
    const float* __restrict__ edge_attr, const void* __restrict__ eidx) {
    __shared__ float v[D_E];
    if (threadIdx.x < D_E) v[threadIdx.x] = g_v[threadIdx.x];
    __syncthreads();

    long long t = (long long)blockIdx.x * 256 + threadIdx.x;
    long long e = t >> 2;
    int q = (int)(t & 3);
    if (e >= N_EDGE) return;

    const float4* row = (const float4*)(edge_attr + e * D_E);
    float p = 0.f;
#pragma unroll
    for (int i = 0; i < 4; i++) {
        float4 av = __ldcs(&row[q + 4 * i]);
        float4 vv = *(const float4*)&v[4 * (q + 4 * i)];
        p += av.x * vv.x + av.y * vv.y + av.z * vv.z + av.w * vv.w;
    }
    p += __shfl_xor_sync(0xffffffffu, p, 1);
    p += __shfl_xor_sync(0xffffffffu, p, 2);
    if (q == 0) {
        bool is64 = idx_is64(eidx);
        long long src = get_idx(eidx, is64, (size_t)e);
        long long tgt = get_idx(eidx, is64, (size_t)N_EDGE + e);
        float s = p + g_as[src] + g_at[tgt];
        s = (s >= 0.f) ? s : 0.2f * s;
        g_score[e] = s;
        atomicMax(&g_mkey[src], fkey(s));
    }
}

// ---------------- K3: softmax denominators ----------------
__global__ void __launch_bounds__(256) denom_kernel(const void* __restrict__ eidx) {
    long long e = (long long)blockIdx.x * 256 + threadIdx.x;
    if (e >= N_EDGE) return;
    bool is64 = idx_is64(eidx);
    long long src = get_idx(eidx, is64, (size_t)e);
    float s = g_score[e];
    float m = fdecode(g_mkey[src]);
    atomicAdd(&g_denom[src], expf(s - m));
}

// ---------------- K4: bf16-split tensor GEMM + gather + softmax + RMSNorm ----------------
// 128 edges x 64 feats per block (8 warps; warp = 16 edges), mma m16n8k16.
// 3-term bf16 split: C = Ah*Bh + Ah*Bl + Al*Bh  (error ~2^-17).
// A fragments loaded straight from global (each 32B sector consumed once -> __ldcs).
// W pre-split once in init; smem planes XOR-swizzled (k2' = k2 ^ 4*(n&7)).
__global__ void __launch_bounds__(256) out_kernel(
    const float* __restrict__ edge_attr, const void* __restrict__ eidx,
    const float* __restrict__ norm_w, float* __restrict__ out) {
    __shared__ unsigned WhSh[D_E * 32];   // 8 KB
    __shared__ unsigned WlSh[D_E * 32];   // 8 KB

    const bool is64 = idx_is64(eidx);
    const int tid  = threadIdx.x;
    const int lane = tid & 31, warp = tid >> 5;
    const int g = lane >> 2, tig = lane & 3;

    for (int i = tid; i < D_E * 32; i += 256) {
        int n = i >> 5, k2 = i & 31;
        int sidx = n * 32 + (k2 ^ (4 * (n & 7)));
        WhSh[sidx] = g_Wh[i];
        WlSh[sidx] = g_Wl[i];
    }
    __syncthreads();

    const long long e0 = (long long)blockIdx.x * 128;
    const long long eA = e0 + warp * 16 + g;
    const long long eB = eA + 8;
    const size_t rA = (size_t)((eA < N_EDGE) ? eA : (N_EDGE - 1));
    const size_t rB = (size_t)((eB < N_EDGE) ? eB : (N_EDGE - 1));
    const float* __restrict__ pA = edge_attr + rA * D_E;
    const float* __restrict__ pB = edge_attr + rB * D_E;

    float c[8][4];
#pragma unroll
    for (int nt = 0; nt < 8; nt++)
#pragma unroll
        for (int r = 0; r < 4; r++) c[nt][r] = 0.f;

#pragma unroll
    for (int kt = 0; kt < 4; kt++) {
        const int kb = 16 * kt + 2 * tig;
        float2 v0 = __ldcs((const float2*)(pA + kb));
        float2 v1 = __ldcs((const float2*)(pB + kb));
        float2 v2 = __ldcs((const float2*)(pA + kb + 8));
        float2 v3 = __ldcs((const float2*)(pB + kb + 8));
        unsigned ah[4], al[4];
        bf16_split2(v0.x, v0.y, ah[0], al[0]);
        bf16_split2(v1.x, v1.y, ah[1], al[1]);
        bf16_split2(v2.x, v2.y, ah[2], al[2]);
        bf16_split2(v3.x, v3.y, ah[3], al[3]);

        const int kx0 = (8 * kt + tig) ^ (4 * g);
        const int kx1 = (8 * kt + tig + 4) ^ (4 * g);
#pragma unroll
        for (int nt = 0; nt < 8; nt++) {
            const int nb = (8 * nt + g) * 32;
            unsigned bh0 = WhSh[nb + kx0], bh1 = WhSh[nb + kx1];
            unsigned bl0 = WlSh[nb + kx0], bl1 = WlSh[nb + kx1];
            mma_bf16(c[nt], ah, bh0, bh1);
            mma_bf16(c[nt], ah, bl0, bl1);
            mma_bf16(c[nt], al, bh0, bh1);
        }
    }

    // ---- epilogue in fragment layout: rows eA (c0,c1) and eB (c2,c3), cols 8*nt+2*tig ----
    bool vA = (eA < N_EDGE), vB = (eB < N_EDGE);

    float2 nw[8];
#pragma unroll
    for (int nt = 0; nt < 8; nt++)
        nw[nt] = __ldg(&((const float2*)norm_w)[nt * 4 + tig]);

    float alphaA = 0.f, alphaB = 0.f;
    if (vA) {
        long long src = get_idx(eidx, is64, (size_t)eA);
        long long tgt = get_idx(eidx, is64, (size_t)N_EDGE + eA);
        float s = g_score[eA];
        alphaA = expf(s - fdecode(g_mkey[src])) / g_denom[src];
        const float2* hs = (const float2*)&g_hs[src * D_E];
        const float2* ht = (const float2*)&g_ht[tgt * D_E];
#pragma unroll
        for (int nt = 0; nt < 8; nt++) {
            float2 a = hs[nt * 4 + tig], b = ht[nt * 4 + tig];
            c[nt][0] += a.x + b.x;
            c[nt][1] += a.y + b.y;
        }
    }
    if (vB) {
        long long src = get_idx(eidx, is64, (size_t)eB);
        long long tgt = get_idx(eidx, is64, (size_t)N_EDGE + eB);
        float s = g_score[eB];
        alphaB = expf(s - fdecode(g_mkey[src])) / g_denom[src];
        const float2* hs = (const float2*)&g_hs[src * D_E];
        const float2* ht = (const float2*)&g_ht[tgt * D_E];
#pragma unroll
        for (int nt = 0; nt < 8; nt++) {
            float2 a = hs[nt * 4 + tig], b = ht[nt * 4 + tig];
            c[nt][2] += a.x + b.x;
            c[nt][3] += a.y + b.y;
        }
    }

    float ssA = 0.f, ssB = 0.f;
#pragma unroll
    for (int nt = 0; nt < 8; nt++) {
        c[nt][0] *= alphaA; c[nt][1] *= alphaA;
        c[nt][2] *= alphaB; c[nt][3] *= alphaB;
        ssA += c[nt][0] * c[nt][0] + c[nt][1] * c[nt][1];
        ssB += c[nt][2] * c[nt][2] + c[nt][3] * c[nt][3];
    }
    ssA += __shfl_xor_sync(0xffffffffu, ssA, 1);
    ssA += __shfl_xor_sync(0xffffffffu, ssA, 2);
    ssB += __shfl_xor_sync(0xffffffffu, ssB, 1);
    ssB += __shfl_xor_sync(0xffffffffu, ssB, 2);
    float rmsA = rsqrtf(ssA * (1.f / 64.f) + 1.1920929e-7f);
    float rmsB = rsqrtf(ssB * (1.f / 64.f) + 1.1920929e-7f);

    if (vA) {
        float2* o = (float2*)&out[eA * D_E];
#pragma unroll
        for (int nt = 0; nt < 8; nt++)
            o[nt * 4 + tig] = make_float2(c[nt][0] * rmsA * nw[nt].x,
                                          c[nt][1] * rmsA * nw[nt].y);
    }
    if (vB) {
        float2* o = (float2*)&out[eB * D_E];
#pragma unroll
        for (int nt = 0; nt < 8; nt++)
            o[nt * 4 + tig] = make_float2(c[nt][2] * rmsB * nw[nt].x,
                                          c[nt][3] * rmsB * nw[nt].y);
    }
}

// ---------------- launch ----------------
extern "C" void kernel_launch(void* const* d_in, const int* in_sizes, int n_in,
                              void* d_out, int out_size) {
    const float* x_s    = (const float*)d_in[0];
    const float* x_t    = (const float*)d_in[1];
    const void*  eidx   = d_in[2];
    const float* ea     = (const float*)d_in[3];
    const float* W_src  = (const float*)d_in[5];
    const float* W_tgt  = (const float*)d_in[6];
    const float* W_edge = (const float*)d_in[7];
    const float* w_attn = (const float*)d_in[8];
    const float* norm_w = (const float*)d_in[9];
    float* out = (float*)d_out;

    init_kernel<<<(N_NODE + 255) / 256, 256>>>(W_edge, w_attn);

    dim3 g1((N_NODE + 255) / 256, 2);
    node_proj_kernel<<<g1, 256>>>(x_s, x_t, W_src, W_tgt, w_attn);

    long long score_threads = (long long)N_EDGE * 4;
    score_kernel<<<(unsigned)((score_threads + 255) / 256), 256>>>(ea, eidx);

    denom_kernel<<<(N_EDGE + 255) / 256, 256>>>(eidx);

    out_kernel<<<(N_EDGE + 127) / 128, 256>>>(ea, eidx, norm_w, out);
}

// round 4
// speedup vs baseline: 1.8004x; 1.0393x over previous
#include <cuda_runtime.h>
#include <math.h>

#define N_NODE  50000
#define N_EDGE  1000000
#define D_E     64
#define D_IN    128

// ---------------- device scratch (static; no allocations allowed) ----------------
__device__ float    g_hs[N_NODE * D_E];     // x_s @ W_src^T   (feature-major)
__device__ float    g_ht[N_NODE * D_E];     // x_t @ W_tgt^T
__device__ float    g_as[N_NODE];           // hs . w_attn
__device__ float    g_at[N_NODE];           // ht . w_attn
__device__ float    g_v[D_E];               // W_edge^T @ w_attn
__device__ unsigned g_mkey[N_NODE];         // ordered-float max keys per src
__device__ float    g_denom[N_NODE];        // softmax denominators per src
__device__ float    g_score[N_EDGE];        // post-leaky scores
// W_edge pre-split bf16 hi/lo, pre-permuted (feature+k perms), 16B groups,
// bank-swizzled: slot(n,kt,tig) = n*16 + 4*(kt^(n&1)) + (tig ^ ((n>>1)&3))
__device__ uint4    g_Wg[D_E * 16];

// ---------------- helpers ----------------
__device__ __forceinline__ unsigned fkey(float f) {
    unsigned u = __float_as_uint(f);
    return (u & 0x80000000u) ? ~u : (u | 0x80000000u);
}
__device__ __forceinline__ float fdecode(unsigned k) {
    return (k & 0x80000000u) ? __uint_as_float(k & 0x7fffffffu)
                             : __uint_as_float(~k);
}
__device__ __forceinline__ bool idx_is64(const void* p) {
    const long long* q = (const long long*)p;
    bool ok = true;
#pragma unroll
    for (int i = 0; i < 4; i++)
        ok = ok && ((unsigned long long)q[i] < (unsigned long long)N_NODE);
    return ok;
}
__device__ __forceinline__ long long get_idx(const void* p, bool is64, size_t pos) {
    return is64 ? ((const long long*)p)[pos]
                : (long long)((const int*)p)[pos];
}
// pack float pair -> bf16x2 hi plane + bf16x2 residual lo plane
__device__ __forceinline__ void bf16_split2(float x0, float x1, unsigned& hi, unsigned& lo) {
    unsigned h;
    asm("cvt.rn.bf16x2.f32 %0, %1, %2;" : "=r"(h) : "f"(x1), "f"(x0));
    float h0 = __uint_as_float(h << 16);
    float h1 = __uint_as_float(h & 0xFFFF0000u);
    unsigned l;
    asm("cvt.rn.bf16x2.f32 %0, %1, %2;" : "=r"(l) : "f"(x1 - h1), "f"(x0 - h0));
    hi = h; lo = l;
}
__device__ __forceinline__ void mma_bf16(float c[4], const unsigned a[4], unsigned b0, unsigned b1) {
    asm volatile(
        "mma.sync.aligned.m16n8k16.row.col.f32.bf16.bf16.f32 "
        "{%0,%1,%2,%3}, {%4,%5,%6,%7}, {%8,%9}, {%0,%1,%2,%3};"
        : "+f"(c[0]), "+f"(c[1]), "+f"(c[2]), "+f"(c[3])
        : "r"(a[0]), "r"(a[1]), "r"(a[2]), "r"(a[3]), "r"(b0), "r"(b1));
}
// feature permutation: logical MMA column n -> actual feature index
__device__ __forceinline__ int fperm(int n) {
    return 16 * ((n >> 1) & 3) + 2 * (n >> 3) + (n & 1);
}

// ---------------- K1: node projections + all one-time init work ----------------
__global__ void __launch_bounds__(256) node_proj_kernel(
    const float* __restrict__ x_s, const float* __restrict__ x_t,
    const float* __restrict__ W_src, const float* __restrict__ W_tgt,
    const float* __restrict__ W_edge, const float* __restrict__ w_attn) {
    __shared__ float WT[D_IN * D_E];
    __shared__ float wa[D_E];

    const float* x; const float* W; float* hout; float* aout;
    if (blockIdx.y == 0) { x = x_s; W = W_src; hout = g_hs; aout = g_as; }
    else                 { x = x_t; W = W_tgt; hout = g_ht; aout = g_at; }

    int gid = blockIdx.x * 256 + threadIdx.x;
    if (blockIdx.y == 0) {      // one-time init, folded in
        if (gid < N_NODE) { g_mkey[gid] = 0u; g_denom[gid] = 0.f; }
        if (gid < D_E) {
            float s = 0.f;
#pragma unroll 8
            for (int j = 0; j < D_E; j++) s += W_edge[j * D_E + gid] * w_attn[j];
            g_v[gid] = s;
        }
        if (gid < D_E * 16) {   // build pre-split, pre-permuted W groups
            int n = gid >> 4, r = gid & 15;
            int kt = r >> 2, tig = r & 3;
            const float* wr = W_edge + (size_t)fperm(n) * D_E + 16 * kt + 4 * tig;
            unsigned h0, l0, h1, l1;
            bf16_split2(wr[0], wr[1], h0, l0);
            bf16_split2(wr[2], wr[3], h1, l1);
            int slot = n * 16 + 4 * (kt ^ (n & 1)) + (tig ^ ((n >> 1) & 3));
            g_Wg[slot] = make_uint4(h0, h1, l0, l1);
        }
    }

    for (int i = threadIdx.x; i < D_E * D_IN; i += blockDim.x) {
        int j = i >> 7, k = i & 127;
        WT[k * D_E + j] = W[i];
    }
    if (threadIdx.x < D_E) wa[threadIdx.x] = w_attn[threadIdx.x];
    __syncthreads();

    int n = gid;
    if (n >= N_NODE) return;

    float acc[D_E];
#pragma unroll
    for (int j = 0; j < D_E; j++) acc[j] = 0.f;

    const float4* xr = (const float4*)(x + (size_t)n * D_IN);
    for (int kc = 0; kc < 32; kc++) {
        float4 xv = xr[kc];
        float xa[4] = {xv.x, xv.y, xv.z, xv.w};
#pragma unroll
        for (int c = 0; c < 4; c++) {
            const float* wrow = &WT[(4 * kc + c) * D_E];
#pragma unroll
            for (int j4 = 0; j4 < D_E; j4 += 4) {
                float4 w = *(const float4*)&wrow[j4];
                acc[j4 + 0] += xa[c] * w.x;
                acc[j4 + 1] += xa[c] * w.y;
                acc[j4 + 2] += xa[c] * w.z;
                acc[j4 + 3] += xa[c] * w.w;
            }
        }
    }
    float av = 0.f;
#pragma unroll
    for (int j = 0; j < D_E; j++) av += acc[j] * wa[j];
    aout[n] = av;
    float4* ho = (float4*)(hout + (size_t)n * D_E);
#pragma unroll
    for (int j4 = 0; j4 < 16; j4++)
        ho[j4] = make_float4(acc[4 * j4], acc[4 * j4 + 1], acc[4 * j4 + 2], acc[4 * j4 + 3]);
}

// ---------------- K2: per-edge score + atomic segment max ----------------
__global__ void __launch_bounds__(256) score_kernel(
    const float* __restrict__ edge_attr, const void* __restrict__ eidx) {
    __shared__ float v[D_E];
    if (threadIdx.x < D_E) v[threadIdx.x] = g_v[threadIdx.x];
    __syncthreads();

    long long t = (long long)blockIdx.x * 256 + threadIdx.x;
    long long e = t >> 2;
    int q = (int)(t & 3);
    if (e >= N_EDGE) return;

    const float4* row = (const float4*)(edge_attr + e * D_E);
    float p = 0.f;
#pragma unroll
    for (int i = 0; i < 4; i++) {
        float4 av = __ldcs(&row[q + 4 * i]);
        float4 vv = *(const float4*)&v[4 * (q + 4 * i)];
        p += av.x * vv.x + av.y * vv.y + av.z * vv.z + av.w * vv.w;
    }
    p += __shfl_xor_sync(0xffffffffu, p, 1);
    p += __shfl_xor_sync(0xffffffffu, p, 2);
    if (q == 0) {
        bool is64 = idx_is64(eidx);
        long long src = get_idx(eidx, is64, (size_t)e);
        long long tgt = get_idx(eidx, is64, (size_t)N_EDGE + e);
        float s = p + g_as[src] + g_at[tgt];
        s = (s >= 0.f) ? s : 0.2f * s;
        g_score[e] = s;
        atomicMax(&g_mkey[src], fkey(s));
    }
}

// ---------------- K3: softmax denominators ----------------
__global__ void __launch_bounds__(256) denom_kernel(const void* __restrict__ eidx) {
    long long e = (long long)blockIdx.x * 256 + threadIdx.x;
    if (e >= N_EDGE) return;
    bool is64 = idx_is64(eidx);
    long long src = get_idx(eidx, is64, (size_t)e);
    float s = g_score[e];
    float m = fdecode(g_mkey[src]);
    atomicAdd(&g_denom[src], __expf(s - m));
}

// ---------------- K4: bf16-split tensor GEMM + gather + softmax + RMSNorm ----------------
// 128 edges x 64 feats per block. Layout permutations make every global access 128-bit:
//  - k-perm: thread's A fragment = 4 consecutive floats  -> LDG.128
//  - feature-perm f=16*tig+2*nt+h: thread's 16 C cols consecutive -> float4 gathers/stores
//  - W pre-split into 16B groups -> one LDS.128 per (kt,nt), bank-conflict-free
__global__ void __launch_bounds__(256) out_kernel(
    const float* __restrict__ edge_attr, const void* __restrict__ eidx,
    const float* __restrict__ norm_w, float* __restrict__ out) {
    __shared__ uint4 Wg[D_E * 16];   // 16 KB

    const bool is64 = idx_is64(eidx);
    const int tid  = threadIdx.x;
    const int lane = tid & 31, warp = tid >> 5;
    const int g = lane >> 2, tig = lane & 3;

    for (int i = tid; i < D_E * 16; i += 256) Wg[i] = g_Wg[i];

    const long long e0 = (long long)blockIdx.x * 128;
    const long long eA = e0 + warp * 16 + g;
    const long long eB = eA + 8;
    const bool vA = (eA < N_EDGE), vB = (eB < N_EDGE);
    const size_t rA = (size_t)(vA ? eA : (N_EDGE - 1));
    const size_t rB = (size_t)(vB ? eB : (N_EDGE - 1));

    // ---- prefetch epilogue metadata early (hide latency under MMA) ----
    const long long sA = get_idx(eidx, is64, rA);
    const long long tA = get_idx(eidx, is64, (size_t)N_EDGE + rA);
    const long long sB = get_idx(eidx, is64, rB);
    const long long tB = get_idx(eidx, is64, (size_t)N_EDGE + rB);
    float aAv = 0.f, aBv = 0.f;
    if (tig == 0) {
        aAv = __expf(g_score[rA] - fdecode(g_mkey[sA])) / g_denom[sA];
        aBv = __expf(g_score[rB] - fdecode(g_mkey[sB])) / g_denom[sB];
    }

    // ---- A loads: 8x LDG.128, phys k = 16*kt + 4*tig (+0..3) ----
    const float4* pA = (const float4*)(edge_attr + rA * D_E);
    const float4* pB = (const float4*)(edge_attr + rB * D_E);
    float4 va[4], vb[4];
#pragma unroll
    for (int kt = 0; kt < 4; kt++) {
        va[kt] = __ldcs(&pA[4 * kt + tig]);
        vb[kt] = __ldcs(&pB[4 * kt + tig]);
    }

    const float alphaA = __shfl_sync(0xffffffffu, aAv, lane & 28);
    const float alphaB = __shfl_sync(0xffffffffu, aBv, lane & 28);

    __syncthreads();

    // ---- MMA mainloop ----
    float c[8][4];
#pragma unroll
    for (int nt = 0; nt < 8; nt++)
#pragma unroll
        for (int r = 0; r < 4; r++) c[nt][r] = 0.f;

    const int bswz = (tig ^ ((g >> 1) & 3));
#pragma unroll
    for (int kt = 0; kt < 4; kt++) {
        unsigned ah[4], al[4];
        bf16_split2(va[kt].x, va[kt].y, ah[0], al[0]);
        bf16_split2(vb[kt].x, vb[kt].y, ah[1], al[1]);
        bf16_split2(va[kt].z, va[kt].w, ah[2], al[2]);
        bf16_split2(vb[kt].z, vb[kt].w, ah[3], al[3]);
        const int koff = 4 * (kt ^ (g & 1)) + bswz;
#pragma unroll
        for (int nt = 0; nt < 8; nt++) {
            uint4 b = Wg[(8 * nt + g) * 16 + koff];
            mma_bf16(c[nt], ah, b.x, b.y);   // Ah*Bh
            mma_bf16(c[nt], ah, b.z, b.w);   // Ah*Bl
            mma_bf16(c[nt], al, b.x, b.y);   // Al*Bh
        }
    }

    // ---- epilogue: thread owns features 16*tig .. 16*tig+15 for rows eA,eB ----
    float4 nw4[4];
#pragma unroll
    for (int q = 0; q < 4; q++)
        nw4[q] = __ldg(&((const float4*)norm_w)[4 * tig + q]);

    // row A
    {
        const float4* hsp = (const float4*)(g_hs + (size_t)sA * D_E + 16 * tig);
        const float4* htp = (const float4*)(g_ht + (size_t)tA * D_E + 16 * tig);
        float4 H[4], T[4];
#pragma unroll
        for (int q = 0; q < 4; q++) { H[q] = hsp[q]; T[q] = htp[q]; }
        float o[16]; float ss = 0.f;
#pragma unroll
        for (int q = 0; q < 4; q++) {
            const float hh[4] = {H[q].x, H[q].y, H[q].z, H[q].w};
            const float tt[4] = {T[q].x, T[q].y, T[q].z, T[q].w};
#pragma unroll
            for (int i = 0; i < 4; i++) {
                int j = 4 * q + i;
                float val = (c[j >> 1][j & 1] + hh[i] + tt[i]) * alphaA;
                ss += val * val;
                o[j] = val;
            }
        }
        ss += __shfl_xor_sync(0xffffffffu, ss, 1);
        ss += __shfl_xor_sync(0xffffffffu, ss, 2);
        float rms = rsqrtf(ss * (1.f / 64.f) + 1.1920929e-7f);
        if (vA) {
            float4* op = (float4*)(out + eA * D_E + 16 * tig);
#pragma unroll
            for (int q = 0; q < 4; q++) {
                float4 w = nw4[q];
                float4 r = make_float4(o[4*q]*rms*w.x, o[4*q+1]*rms*w.y,
                                       o[4*q+2]*rms*w.z, o[4*q+3]*rms*w.w);
                __stcs(&op[q], r);
            }
        }
    }
    // row B
    {
        const float4* hsp = (const float4*)(g_hs + (size_t)sB * D_E + 16 * tig);
        const float4* htp = (const float4*)(g_ht + (size_t)tB * D_E + 16 * tig);
        float4 H[4], T[4];
#pragma unroll
        for (int q = 0; q < 4; q++) { H[q] = hsp[q]; T[q] = htp[q]; }
        float o[16]; float ss = 0.f;
#pragma unroll
        for (int q = 0; q < 4; q++) {
            const float hh[4] = {H[q].x, H[q].y, H[q].z, H[q].w};
            const float tt[4] = {T[q].x, T[q].y, T[q].z, T[q].w};
#pragma unroll
            for (int i = 0; i < 4; i++) {
                int j = 4 * q + i;
                float val = (c[j >> 1][2 + (j & 1)] + hh[i] + tt[i]) * alphaB;
                ss += val * val;
                o[j] = val;
            }
        }
        ss += __shfl_xor_sync(0xffffffffu, ss, 1);
        ss += __shfl_xor_sync(0xffffffffu, ss, 2);
        float rms = rsqrtf(ss * (1.f / 64.f) + 1.1920929e-7f);
        if (vB) {
            float4* op = (float4*)(out + eB * D_E + 16 * tig);
#pragma unroll
            for (int q = 0; q < 4; q++) {
                float4 w = nw4[q];
                float4 r = make_float4(o[4*q]*rms*w.x, o[4*q+1]*rms*w.y,
                                       o[4*q+2]*rms*w.z, o[4*q+3]*rms*w.w);
                __stcs(&op[q], r);
            }
        }
    }
}

// ---------------- launch ----------------
extern "C" void kernel_launch(void* const* d_in, const int* in_sizes, int n_in,
                              void* d_out, int out_size) {
    const float* x_s    = (const float*)d_in[0];
    const float* x_t    = (const float*)d_in[1];
    const void*  eidx   = d_in[2];
    const float* ea     = (const float*)d_in[3];
    const float* W_src  = (const float*)d_in[5];
    const float* W_tgt  = (const float*)d_in[6];
    const float* W_edge = (const float*)d_in[7];
    const float* w_attn = (const float*)d_in[8];
    const float* norm_w = (const float*)d_in[9];
    float* out = (float*)d_out;

    dim3 g1((N_NODE + 255) / 256, 2);
    node_proj_kernel<<<g1, 256>>>(x_s, x_t, W_src, W_tgt, W_edge, w_attn);

    long long score_threads = (long long)N_EDGE * 4;
    score_kernel<<<(unsigned)((score_threads + 255) / 256), 256>>>(ea, eidx);

    denom_kernel<<<(N_EDGE + 255) / 256, 256>>>(eidx);

    out_kernel<<<(N_EDGE + 127) / 128, 256>>>(ea, eidx, norm_w, out);
}